// round 3
// baseline (speedup 1.0000x reference)
#include <cuda_runtime.h>
#include <cuda_fp16.h>

#define NN   50000
#define EE   800000
#define DD   128
#define OUTD 64

// ---------------- device scratch (no allocations allowed) ----------------
__device__ __half g_t16[NN * DD];   // GEMM output (fp16) / aggregation source
__device__ float  g_h1[NN * DD];
__device__ float  g_h2[NN * DD];
__device__ float  g_out_norm[NN];
__device__ float  g_in_norm [NN];
__device__ int    g_deg_in [NN];
__device__ int    g_deg_out[NN];
__device__ int    g_row_start[NN];
__device__ int    g_cnt[NN];
__device__ int    g_col[EE];
__device__ int    g_bsum[64];
__device__ float  g_Wcat[DD * DD];  // [W3 | skip_W] concatenated, 128x128

// ---------------- small helpers ----------------
__device__ __forceinline__ unsigned long long pack_dup(float x) {
    unsigned long long r;
    asm("mov.b64 %0, {%1, %1};" : "=l"(r) : "f"(x));
    return r;
}
__device__ __forceinline__ void unpack2(unsigned long long v, float& lo, float& hi) {
    asm("mov.b64 {%0, %1}, %2;" : "=f"(lo), "=f"(hi) : "l"(v));
}
__device__ __forceinline__ void ffma2(unsigned long long& d, unsigned long long a, unsigned long long b) {
    asm("fma.rn.f32x2 %0, %1, %2, %0;" : "+l"(d) : "l"(a), "l"(b));
}

// ---------------- setup kernels ----------------
__global__ void k_zero() {
    int i = blockIdx.x * blockDim.x + threadIdx.x;
    if (i < NN) { g_deg_in[i] = 0; g_deg_out[i] = 0; g_cnt[i] = 0; }
}

__global__ void k_deg(const int* __restrict__ src, const int* __restrict__ dst) {
    int e = blockIdx.x * blockDim.x + threadIdx.x;
    if (e < EE) {
        atomicAdd(&g_deg_out[src[e]], 1);
        atomicAdd(&g_deg_in [dst[e]], 1);
    }
}

// block-wise exclusive scan of g_deg_in -> g_row_start (partial), block sums to g_bsum
__global__ void k_scan1() {
    __shared__ int sh[1024];
    int i = blockIdx.x * 1024 + threadIdx.x;
    int v = (i < NN) ? g_deg_in[i] : 0;
    sh[threadIdx.x] = v;
    __syncthreads();
    #pragma unroll
    for (int off = 1; off < 1024; off <<= 1) {
        int t = (threadIdx.x >= off) ? sh[threadIdx.x - off] : 0;
        __syncthreads();
        sh[threadIdx.x] += t;
        __syncthreads();
    }
    if (i < NN) g_row_start[i] = sh[threadIdx.x] - v;   // exclusive within block
    if (threadIdx.x == 1023) g_bsum[blockIdx.x] = sh[1023];
}

__global__ void k_scan2(int nblocks) {
    __shared__ int sh[64];
    int t = threadIdx.x;
    int v = (t < nblocks) ? g_bsum[t] : 0;
    sh[t] = v;
    __syncthreads();
    #pragma unroll
    for (int off = 1; off < 64; off <<= 1) {
        int u = (t >= off) ? sh[t - off] : 0;
        __syncthreads();
        sh[t] += u;
        __syncthreads();
    }
    if (t < nblocks) g_bsum[t] = sh[t] - v;  // exclusive
}

// finish scan AND compute norms (merged — both iterate nodes once)
__global__ void k_scan3_norms() {
    int i = blockIdx.x * blockDim.x + threadIdx.x;
    if (i < NN) {
        g_row_start[i] += g_bsum[i >> 10];
        int od = g_deg_out[i], id = g_deg_in[i];
        g_out_norm[i] = rsqrtf((float)(od > 1 ? od : 1));
        g_in_norm [i] = rsqrtf((float)(id > 1 ? id : 1));
    }
}

__global__ void k_fill(const int* __restrict__ src, const int* __restrict__ dst) {
    int e = blockIdx.x * blockDim.x + threadIdx.x;
    if (e < EE) {
        int d = dst[e];
        int p = g_row_start[d] + atomicAdd(&g_cnt[d], 1);
        g_col[p] = src[e];
    }
}

__global__ void k_wcat(const float* __restrict__ W3, const float* __restrict__ skipW) {
    int idx = blockIdx.x * blockDim.x + threadIdx.x;
    if (idx < DD * DD) {
        int k = idx >> 7, n = idx & 127;
        g_Wcat[idx] = (n < OUTD) ? W3[k * OUTD + n] : skipW[k * OUTD + (n - OUTD)];
    }
}

// ---------------- GEMM: C[N x 128] = A[N x 128] @ B[128 x 128] -> fp16 ----------------
// layer 0: A = node_feats (ext), B = W1 (ext), scaleCols = 128
// layer 1: A = g_h1,             B = W2 (ext), scaleCols = 128
// layer 2: A = g_h2,             B = g_Wcat,   scaleCols = 64 (skip half unscaled)
// Rows of C with col < scaleCols are pre-multiplied by out_norm[row]; stored fp16.
__global__ void __launch_bounds__(256) k_gemm(const float* __restrict__ extA,
                                              const float* __restrict__ extB,
                                              int layer, int scaleCols) {
    const float* A = (layer == 0) ? extA : (layer == 1) ? g_h1 : g_h2;
    const float* B = (layer == 2) ? g_Wcat : extB;

    __shared__ float As[16][132];   // [k][m], padded
    __shared__ float Bs[16][128];   // [k][n]

    int tid  = threadIdx.x;
    int row0 = blockIdx.x * 128;
    int tx   = tid & 15;            // n-tile: cols tx*8 .. tx*8+7
    int ty   = tid >> 4;            // m-tile: rows ty*8 .. ty*8+7

    unsigned long long acc[8][4];
    #pragma unroll
    for (int i = 0; i < 8; i++)
        #pragma unroll
        for (int j = 0; j < 4; j++) acc[i][j] = 0ull;

    for (int kt = 0; kt < 128; kt += 16) {
        #pragma unroll
        for (int j = 0; j < 2; j++) {
            int f  = tid + j * 256;
            int r  = f >> 2;
            int kq = f & 3;
            int gr = row0 + r;
            float4 v = make_float4(0.f, 0.f, 0.f, 0.f);
            if (gr < NN) v = *(const float4*)&A[gr * 128 + kt + kq * 4];
            As[kq * 4 + 0][r] = v.x;
            As[kq * 4 + 1][r] = v.y;
            As[kq * 4 + 2][r] = v.z;
            As[kq * 4 + 3][r] = v.w;
        }
        #pragma unroll
        for (int j = 0; j < 2; j++) {
            int f  = tid + j * 256;
            int kr = f >> 5;
            int c4 = f & 31;
            *(float4*)&Bs[kr][c4 * 4] = *(const float4*)&B[(kt + kr) * 128 + c4 * 4];
        }
        __syncthreads();

        #pragma unroll
        for (int kk = 0; kk < 16; kk++) {
            float4 a0 = *(const float4*)&As[kk][ty * 8];
            float4 a1 = *(const float4*)&As[kk][ty * 8 + 4];
            float4 b0 = *(const float4*)&Bs[kk][tx * 8];
            float4 b1 = *(const float4*)&Bs[kk][tx * 8 + 4];
            unsigned long long bp[4];
            bp[0] = *(unsigned long long*)&b0.x;
            bp[1] = *(unsigned long long*)&b0.z;
            bp[2] = *(unsigned long long*)&b1.x;
            bp[3] = *(unsigned long long*)&b1.z;
            unsigned long long ap[8];
            ap[0] = pack_dup(a0.x); ap[1] = pack_dup(a0.y);
            ap[2] = pack_dup(a0.z); ap[3] = pack_dup(a0.w);
            ap[4] = pack_dup(a1.x); ap[5] = pack_dup(a1.y);
            ap[6] = pack_dup(a1.z); ap[7] = pack_dup(a1.w);
            #pragma unroll
            for (int i = 0; i < 8; i++)
                #pragma unroll
                for (int j = 0; j < 4; j++)
                    ffma2(acc[i][j], ap[i], bp[j]);
        }
        __syncthreads();
    }

    // epilogue: optional out_norm row scaling, convert to fp16, 16B store
    bool doScale = (tx * 8) < scaleCols;
    #pragma unroll
    for (int i = 0; i < 8; i++) {
        int r = row0 + ty * 8 + i;
        if (r >= NN) break;
        float sc = doScale ? g_out_norm[r] : 1.0f;
        union { uint4 u; __half2 h[4]; } pk;
        #pragma unroll
        for (int j = 0; j < 4; j++) {
            float lo, hi;
            unpack2(acc[i][j], lo, hi);
            pk.h[j] = __floats2half2_rn(lo * sc, hi * sc);
        }
        *(uint4*)&g_t16[r * 128 + tx * 8] = pk.u;
    }
}

// ---------------- aggregation (CSR gather-sum, fp16 source) + epilogues ----------------
// EPI 1: h1 = relu(in_norm*acc + b1)                       (D=128, writes g_h1)
// EPI 2: h2 = relu(0.6*h1 + 0.4*(in_norm*acc + b2))        (D=128, writes g_h2)
// EPI 3: out = 0.6*(skip + skip_b) + 0.4*(in_norm*acc+b3)  (D=64,  writes extOut)
//        skip read from g_t16 cols 64..127 of the same row.
// Destinations are selected IN DEVICE CODE (device symbols never passed from host).
template <int EPI>
__global__ void __launch_bounds__(256) k_agg(const float* __restrict__ bmain,
                                             const float* __restrict__ baux,
                                             float* __restrict__ extOut) {
    // 32 lanes per node. D=128: lane holds 4 channels (uint2 = 4 halves).
    // D=64 (EPI 3): lane holds 2 channels (uint = half2).
    int node = blockIdx.x * 8 + (threadIdx.x >> 5);
    int g    = threadIdx.x & 31;
    if (node >= NN) return;

    int e   = g_row_start[node];
    int end = e + g_deg_in[node];

    if (EPI != 3) {
        const uint2* X = (const uint2*)g_t16;   // row stride = 32 uint2
        float4 acc = make_float4(0.f, 0.f, 0.f, 0.f);
        for (; e + 4 <= end; e += 4) {
            int s0 = g_col[e], s1 = g_col[e + 1], s2 = g_col[e + 2], s3 = g_col[e + 3];
            uint2 u0 = X[s0 * 32 + g];
            uint2 u1 = X[s1 * 32 + g];
            uint2 u2 = X[s2 * 32 + g];
            uint2 u3 = X[s3 * 32 + g];
            float2 a0 = __half22float2(*(__half2*)&u0.x), b0 = __half22float2(*(__half2*)&u0.y);
            float2 a1 = __half22float2(*(__half2*)&u1.x), b1 = __half22float2(*(__half2*)&u1.y);
            float2 a2 = __half22float2(*(__half2*)&u2.x), b2 = __half22float2(*(__half2*)&u2.y);
            float2 a3 = __half22float2(*(__half2*)&u3.x), b3 = __half22float2(*(__half2*)&u3.y);
            acc.x += (a0.x + a1.x) + (a2.x + a3.x);
            acc.y += (a0.y + a1.y) + (a2.y + a3.y);
            acc.z += (b0.x + b1.x) + (b2.x + b3.x);
            acc.w += (b0.y + b1.y) + (b2.y + b3.y);
        }
        for (; e < end; ++e) {
            uint2 u = X[g_col[e] * 32 + g];
            float2 a = __half22float2(*(__half2*)&u.x), b = __half22float2(*(__half2*)&u.y);
            acc.x += a.x; acc.y += a.y; acc.z += b.x; acc.w += b.y;
        }

        float w = g_in_norm[node];
        float4 b = ((const float4*)bmain)[g];
        float4 r;
        if (EPI == 1) {
            r.x = fmaxf(acc.x * w + b.x, 0.f);
            r.y = fmaxf(acc.y * w + b.y, 0.f);
            r.z = fmaxf(acc.z * w + b.z, 0.f);
            r.w = fmaxf(acc.w * w + b.w, 0.f);
            ((float4*)g_h1)[node * 32 + g] = r;
        } else {
            float4 hp = ((const float4*)g_h1)[node * 32 + g];
            r.x = fmaxf(0.6f * hp.x + 0.4f * (acc.x * w + b.x), 0.f);
            r.y = fmaxf(0.6f * hp.y + 0.4f * (acc.y * w + b.y), 0.f);
            r.z = fmaxf(0.6f * hp.z + 0.4f * (acc.z * w + b.z), 0.f);
            r.w = fmaxf(0.6f * hp.w + 0.4f * (acc.w * w + b.w), 0.f);
            ((float4*)g_h2)[node * 32 + g] = r;
        }
    } else {
        const __half2* X = (const __half2*)g_t16;   // row stride = 64 half2
        float2 acc = make_float2(0.f, 0.f);
        for (; e + 4 <= end; e += 4) {
            int s0 = g_col[e], s1 = g_col[e + 1], s2 = g_col[e + 2], s3 = g_col[e + 3];
            float2 a0 = __half22float2(X[s0 * 64 + g]);
            float2 a1 = __half22float2(X[s1 * 64 + g]);
            float2 a2 = __half22float2(X[s2 * 64 + g]);
            float2 a3 = __half22float2(X[s3 * 64 + g]);
            acc.x += (a0.x + a1.x) + (a2.x + a3.x);
            acc.y += (a0.y + a1.y) + (a2.y + a3.y);
        }
        for (; e < end; ++e) {
            float2 a = __half22float2(X[g_col[e] * 64 + g]);
            acc.x += a.x; acc.y += a.y;
        }

        float w = g_in_norm[node];
        float2 b  = ((const float2*)bmain)[g];
        float2 sb = ((const float2*)baux)[g];
        float2 s2 = __half22float2(X[node * 64 + 32 + g]);   // skip half (unscaled)
        float2 r;
        r.x = 0.6f * (s2.x + sb.x) + 0.4f * (acc.x * w + b.x);
        r.y = 0.6f * (s2.y + sb.y) + 0.4f * (acc.y * w + b.y);
        ((float2*)extOut)[node * 32 + g] = r;
    }
}

// ---------------- host launcher ----------------
extern "C" void kernel_launch(void* const* d_in, const int* in_sizes, int n_in,
                              void* d_out, int out_size) {
    const float* node_feats = (const float*)d_in[0];
    const int*   edge_index = (const int*)d_in[1];
    const float* W1    = (const float*)d_in[2];
    const float* b1    = (const float*)d_in[3];
    const float* W2    = (const float*)d_in[4];
    const float* b2    = (const float*)d_in[5];
    const float* W3    = (const float*)d_in[6];
    const float* b3    = (const float*)d_in[7];
    const float* skipW = (const float*)d_in[8];
    const float* skipb = (const float*)d_in[9];
    float* out = (float*)d_out;

    const int* src = edge_index;
    const int* dst = edge_index + EE;

    const int TB = 256;
    int nb_nodes = (NN + TB - 1) / TB;
    int nb_edges = (EE + TB - 1) / TB;
    int nb_scan  = (NN + 1023) / 1024;   // 49
    int nb_gemm  = (NN + 127) / 128;     // 391

    // graph structure (rebuilt every call — deterministic work)
    k_zero <<<nb_nodes, TB>>>();
    k_deg  <<<nb_edges, TB>>>(src, dst);
    k_scan1<<<nb_scan, 1024>>>();
    k_scan2<<<1, 64>>>(nb_scan);
    k_scan3_norms<<<nb_nodes, TB>>>();
    k_fill <<<nb_edges, TB>>>(src, dst);
    k_wcat <<<(DD * DD + TB - 1) / TB, TB>>>(W3, skipW);

    // layer 1
    k_gemm  <<<nb_gemm, 256>>>(node_feats, W1, 0, 128);
    k_agg<1><<<(NN + 7) / 8, 256>>>(b1, nullptr, nullptr);
    // layer 2
    k_gemm  <<<nb_gemm, 256>>>(nullptr, W2, 1, 128);
    k_agg<2><<<(NN + 7) / 8, 256>>>(b2, nullptr, nullptr);
    // layer 3 (W3 | skip_W fused GEMM; only W3 half out_norm-scaled)
    k_gemm  <<<nb_gemm, 256>>>(nullptr, nullptr, 2, 64);
    k_agg<3><<<(NN + 7) / 8, 256>>>(b3, skipb, out);
}

// round 4
// speedup vs baseline: 1.3865x; 1.3865x over previous
#include <cuda_runtime.h>
#include <cuda_fp16.h>

#define NN   50000
#define EE   800000
#define DD   128
#define OUTD 64

// ---------------- device scratch (no allocations allowed) ----------------
__device__ __half g_t16[NN * DD];   // GEMM output (fp16) / aggregation source
__device__ float  g_h1[NN * DD];
__device__ float  g_h2[NN * DD];
__device__ float  g_out_norm[NN];
__device__ float  g_in_norm [NN];
__device__ int    g_deg_in [NN];
__device__ int    g_deg_out[NN];
__device__ int    g_row_start[NN];
__device__ int    g_cnt[NN];
__device__ int    g_col[EE];
__device__ int    g_bsum[64];
__device__ float  g_Wcat[DD * DD];  // [W3 | skip_W] concatenated, 128x128

// ---------------- small helpers ----------------
__device__ __forceinline__ unsigned long long pack_dup(float x) {
    unsigned long long r;
    asm("mov.b64 %0, {%1, %1};" : "=l"(r) : "f"(x));
    return r;
}
__device__ __forceinline__ void unpack2(unsigned long long v, float& lo, float& hi) {
    asm("mov.b64 {%0, %1}, %2;" : "=f"(lo), "=f"(hi) : "l"(v));
}
__device__ __forceinline__ void ffma2(unsigned long long& d, unsigned long long a, unsigned long long b) {
    asm("fma.rn.f32x2 %0, %1, %2, %0;" : "+l"(d) : "l"(a), "l"(b));
}
__device__ __forceinline__ __half2 u2h(unsigned int u) { return *(__half2*)&u; }

// ---------------- setup kernels ----------------
__global__ void k_zero() {
    int i = blockIdx.x * blockDim.x + threadIdx.x;
    if (i < NN) { g_deg_in[i] = 0; g_deg_out[i] = 0; g_cnt[i] = 0; }
}

__global__ void k_deg(const int* __restrict__ src, const int* __restrict__ dst) {
    int e = blockIdx.x * blockDim.x + threadIdx.x;
    if (e < EE) {
        atomicAdd(&g_deg_out[src[e]], 1);
        atomicAdd(&g_deg_in [dst[e]], 1);
    }
}

// block-wise exclusive scan of g_deg_in -> g_row_start (partial), block sums to g_bsum
__global__ void k_scan1() {
    __shared__ int sh[1024];
    int i = blockIdx.x * 1024 + threadIdx.x;
    int v = (i < NN) ? g_deg_in[i] : 0;
    sh[threadIdx.x] = v;
    __syncthreads();
    #pragma unroll
    for (int off = 1; off < 1024; off <<= 1) {
        int t = (threadIdx.x >= off) ? sh[threadIdx.x - off] : 0;
        __syncthreads();
        sh[threadIdx.x] += t;
        __syncthreads();
    }
    if (i < NN) g_row_start[i] = sh[threadIdx.x] - v;   // exclusive within block
    if (threadIdx.x == 1023) g_bsum[blockIdx.x] = sh[1023];
}

__global__ void k_scan2(int nblocks) {
    __shared__ int sh[64];
    int t = threadIdx.x;
    int v = (t < nblocks) ? g_bsum[t] : 0;
    sh[t] = v;
    __syncthreads();
    #pragma unroll
    for (int off = 1; off < 64; off <<= 1) {
        int u = (t >= off) ? sh[t - off] : 0;
        __syncthreads();
        sh[t] += u;
        __syncthreads();
    }
    if (t < nblocks) g_bsum[t] = sh[t] - v;  // exclusive
}

// finish scan AND compute norms (merged — both iterate nodes once)
__global__ void k_scan3_norms() {
    int i = blockIdx.x * blockDim.x + threadIdx.x;
    if (i < NN) {
        g_row_start[i] += g_bsum[i >> 10];
        int od = g_deg_out[i], id = g_deg_in[i];
        g_out_norm[i] = rsqrtf((float)(od > 1 ? od : 1));
        g_in_norm [i] = rsqrtf((float)(id > 1 ? id : 1));
    }
}

__global__ void k_fill(const int* __restrict__ src, const int* __restrict__ dst) {
    int e = blockIdx.x * blockDim.x + threadIdx.x;
    if (e < EE) {
        int d = dst[e];
        int p = g_row_start[d] + atomicAdd(&g_cnt[d], 1);
        g_col[p] = src[e];
    }
}

__global__ void k_wcat(const float* __restrict__ W3, const float* __restrict__ skipW) {
    int idx = blockIdx.x * blockDim.x + threadIdx.x;
    if (idx < DD * DD) {
        int k = idx >> 7, n = idx & 127;
        g_Wcat[idx] = (n < OUTD) ? W3[k * OUTD + n] : skipW[k * OUTD + (n - OUTD)];
    }
}

// ---------------- GEMM: C[N x 128] = A[N x 128] @ B[128 x 128] -> fp16 ----------------
// layer 0: A = node_feats (ext), B = W1 (ext), scaleCols = 128
// layer 1: A = g_h1,             B = W2 (ext), scaleCols = 128
// layer 2: A = g_h2,             B = g_Wcat,   scaleCols = 64 (skip half unscaled)
// Rows of C with col < scaleCols are pre-multiplied by out_norm[row]; stored fp16.
__global__ void __launch_bounds__(256) k_gemm(const float* __restrict__ extA,
                                              const float* __restrict__ extB,
                                              int layer, int scaleCols) {
    const float* A = (layer == 0) ? extA : (layer == 1) ? g_h1 : g_h2;
    const float* B = (layer == 2) ? g_Wcat : extB;

    __shared__ float As[16][132];   // [k][m], padded
    __shared__ float Bs[16][128];   // [k][n]

    int tid  = threadIdx.x;
    int row0 = blockIdx.x * 128;
    int tx   = tid & 15;            // n-tile: cols tx*8 .. tx*8+7
    int ty   = tid >> 4;            // m-tile: rows ty*8 .. ty*8+7

    unsigned long long acc[8][4];
    #pragma unroll
    for (int i = 0; i < 8; i++)
        #pragma unroll
        for (int j = 0; j < 4; j++) acc[i][j] = 0ull;

    for (int kt = 0; kt < 128; kt += 16) {
        #pragma unroll
        for (int j = 0; j < 2; j++) {
            int f  = tid + j * 256;
            int r  = f >> 2;
            int kq = f & 3;
            int gr = row0 + r;
            float4 v = make_float4(0.f, 0.f, 0.f, 0.f);
            if (gr < NN) v = *(const float4*)&A[gr * 128 + kt + kq * 4];
            As[kq * 4 + 0][r] = v.x;
            As[kq * 4 + 1][r] = v.y;
            As[kq * 4 + 2][r] = v.z;
            As[kq * 4 + 3][r] = v.w;
        }
        #pragma unroll
        for (int j = 0; j < 2; j++) {
            int f  = tid + j * 256;
            int kr = f >> 5;
            int c4 = f & 31;
            *(float4*)&Bs[kr][c4 * 4] = *(const float4*)&B[(kt + kr) * 128 + c4 * 4];
        }
        __syncthreads();

        #pragma unroll
        for (int kk = 0; kk < 16; kk++) {
            float4 a0 = *(const float4*)&As[kk][ty * 8];
            float4 a1 = *(const float4*)&As[kk][ty * 8 + 4];
            float4 b0 = *(const float4*)&Bs[kk][tx * 8];
            float4 b1 = *(const float4*)&Bs[kk][tx * 8 + 4];
            unsigned long long bp[4];
            bp[0] = *(unsigned long long*)&b0.x;
            bp[1] = *(unsigned long long*)&b0.z;
            bp[2] = *(unsigned long long*)&b1.x;
            bp[3] = *(unsigned long long*)&b1.z;
            unsigned long long ap[8];
            ap[0] = pack_dup(a0.x); ap[1] = pack_dup(a0.y);
            ap[2] = pack_dup(a0.z); ap[3] = pack_dup(a0.w);
            ap[4] = pack_dup(a1.x); ap[5] = pack_dup(a1.y);
            ap[6] = pack_dup(a1.z); ap[7] = pack_dup(a1.w);
            #pragma unroll
            for (int i = 0; i < 8; i++)
                #pragma unroll
                for (int j = 0; j < 4; j++)
                    ffma2(acc[i][j], ap[i], bp[j]);
        }
        __syncthreads();
    }

    // epilogue: optional out_norm row scaling, convert to fp16, 16B store
    bool doScale = (tx * 8) < scaleCols;
    #pragma unroll
    for (int i = 0; i < 8; i++) {
        int r = row0 + ty * 8 + i;
        if (r >= NN) break;
        float sc = doScale ? g_out_norm[r] : 1.0f;
        union { uint4 u; __half2 h[4]; } pk;
        #pragma unroll
        for (int j = 0; j < 4; j++) {
            float lo, hi;
            unpack2(acc[i][j], lo, hi);
            pk.h[j] = __floats2half2_rn(lo * sc, hi * sc);
        }
        *(uint4*)&g_t16[r * 128 + tx * 8] = pk.u;
    }
}

// ---------------- aggregation (CSR gather-sum, fp16 + HADD2 tree) + epilogues -----
// Key change vs R3: 4-edge groups are summed in fp16 with HADD2 (fma pipe,
// cheap) and converted to fp32 ONCE per group — 4x fewer slow F2F conversions.
// EPI 1: h1 = relu(in_norm*acc + b1)                       (D=128, writes g_h1)
// EPI 2: h2 = relu(0.6*h1 + 0.4*(in_norm*acc + b2))        (D=128, writes g_h2)
// EPI 3: out = 0.6*(skip + skip_b) + 0.4*(in_norm*acc+b3)  (D=64,  writes extOut)
template <int EPI>
__global__ void __launch_bounds__(256) k_agg(const float* __restrict__ bmain,
                                             const float* __restrict__ baux,
                                             float* __restrict__ extOut) {
    int node = blockIdx.x * 8 + (threadIdx.x >> 5);
    int g    = threadIdx.x & 31;
    if (node >= NN) return;

    int e   = g_row_start[node];
    int end = e + g_deg_in[node];

    if (EPI != 3) {
        const uint2* X = (const uint2*)g_t16;   // row stride = 32 uint2 (4 halves/lane)
        float4 acc = make_float4(0.f, 0.f, 0.f, 0.f);
        for (; e + 4 <= end; e += 4) {
            int s0 = g_col[e], s1 = g_col[e + 1], s2 = g_col[e + 2], s3 = g_col[e + 3];
            uint2 u0 = X[s0 * 32 + g];
            uint2 u1 = X[s1 * 32 + g];
            uint2 u2 = X[s2 * 32 + g];
            uint2 u3 = X[s3 * 32 + g];
            __half2 xs = __hadd2(__hadd2(u2h(u0.x), u2h(u1.x)),
                                 __hadd2(u2h(u2.x), u2h(u3.x)));
            __half2 ys = __hadd2(__hadd2(u2h(u0.y), u2h(u1.y)),
                                 __hadd2(u2h(u2.y), u2h(u3.y)));
            float2 fx = __half22float2(xs);
            float2 fy = __half22float2(ys);
            acc.x += fx.x; acc.y += fx.y; acc.z += fy.x; acc.w += fy.y;
        }
        for (; e < end; ++e) {
            uint2 u = X[g_col[e] * 32 + g];
            float2 a = __half22float2(u2h(u.x)), b = __half22float2(u2h(u.y));
            acc.x += a.x; acc.y += a.y; acc.z += b.x; acc.w += b.y;
        }

        float w = g_in_norm[node];
        float4 b = ((const float4*)bmain)[g];
        float4 r;
        if (EPI == 1) {
            r.x = fmaxf(acc.x * w + b.x, 0.f);
            r.y = fmaxf(acc.y * w + b.y, 0.f);
            r.z = fmaxf(acc.z * w + b.z, 0.f);
            r.w = fmaxf(acc.w * w + b.w, 0.f);
            ((float4*)g_h1)[node * 32 + g] = r;
        } else {
            float4 hp = ((const float4*)g_h1)[node * 32 + g];
            r.x = fmaxf(0.6f * hp.x + 0.4f * (acc.x * w + b.x), 0.f);
            r.y = fmaxf(0.6f * hp.y + 0.4f * (acc.y * w + b.y), 0.f);
            r.z = fmaxf(0.6f * hp.z + 0.4f * (acc.z * w + b.z), 0.f);
            r.w = fmaxf(0.6f * hp.w + 0.4f * (acc.w * w + b.w), 0.f);
            ((float4*)g_h2)[node * 32 + g] = r;
        }
    } else {
        const unsigned int* X = (const unsigned int*)g_t16;  // row stride = 64 half2
        float2 acc = make_float2(0.f, 0.f);
        for (; e + 4 <= end; e += 4) {
            int s0 = g_col[e], s1 = g_col[e + 1], s2 = g_col[e + 2], s3 = g_col[e + 3];
            unsigned int u0 = X[s0 * 64 + g];
            unsigned int u1 = X[s1 * 64 + g];
            unsigned int u2 = X[s2 * 64 + g];
            unsigned int u3 = X[s3 * 64 + g];
            __half2 s = __hadd2(__hadd2(u2h(u0), u2h(u1)),
                                __hadd2(u2h(u2), u2h(u3)));
            float2 f = __half22float2(s);
            acc.x += f.x; acc.y += f.y;
        }
        for (; e < end; ++e) {
            float2 a = __half22float2(u2h(X[g_col[e] * 64 + g]));
            acc.x += a.x; acc.y += a.y;
        }

        float w = g_in_norm[node];
        float2 b  = ((const float2*)bmain)[g];
        float2 sb = ((const float2*)baux)[g];
        float2 s2 = __half22float2(u2h(X[node * 64 + 32 + g]));  // skip half (unscaled)
        float2 r;
        r.x = 0.6f * (s2.x + sb.x) + 0.4f * (acc.x * w + b.x);
        r.y = 0.6f * (s2.y + sb.y) + 0.4f * (acc.y * w + b.y);
        ((float2*)extOut)[node * 32 + g] = r;
    }
}

// ---------------- host launcher ----------------
extern "C" void kernel_launch(void* const* d_in, const int* in_sizes, int n_in,
                              void* d_out, int out_size) {
    const float* node_feats = (const float*)d_in[0];
    const int*   edge_index = (const int*)d_in[1];
    const float* W1    = (const float*)d_in[2];
    const float* b1    = (const float*)d_in[3];
    const float* W2    = (const float*)d_in[4];
    const float* b2    = (const float*)d_in[5];
    const float* W3    = (const float*)d_in[6];
    const float* b3    = (const float*)d_in[7];
    const float* skipW = (const float*)d_in[8];
    const float* skipb = (const float*)d_in[9];
    float* out = (float*)d_out;

    const int* src = edge_index;
    const int* dst = edge_index + EE;

    const int TB = 256;
    int nb_nodes = (NN + TB - 1) / TB;
    int nb_edges = (EE + TB - 1) / TB;
    int nb_scan  = (NN + 1023) / 1024;   // 49
    int nb_gemm  = (NN + 127) / 128;     // 391

    // graph structure (rebuilt every call — deterministic work)
    k_zero <<<nb_nodes, TB>>>();
    k_deg  <<<nb_edges, TB>>>(src, dst);
    k_scan1<<<nb_scan, 1024>>>();
    k_scan2<<<1, 64>>>(nb_scan);
    k_scan3_norms<<<nb_nodes, TB>>>();
    k_fill <<<nb_edges, TB>>>(src, dst);
    k_wcat <<<(DD * DD + TB - 1) / TB, TB>>>(W3, skipW);

    // layer 1
    k_gemm  <<<nb_gemm, 256>>>(node_feats, W1, 0, 128);
    k_agg<1><<<(NN + 7) / 8, 256>>>(b1, nullptr, nullptr);
    // layer 2
    k_gemm  <<<nb_gemm, 256>>>(nullptr, W2, 1, 128);
    k_agg<2><<<(NN + 7) / 8, 256>>>(b2, nullptr, nullptr);
    // layer 3 (W3 | skip_W fused GEMM; only W3 half out_norm-scaled)
    k_gemm  <<<nb_gemm, 256>>>(nullptr, nullptr, 2, 64);
    k_agg<3><<<(NN + 7) / 8, 256>>>(b3, skipb, out);
}

// round 5
// speedup vs baseline: 2.2364x; 1.6130x over previous
#include <cuda_runtime.h>
#include <cuda_fp16.h>

#define NN   50000
#define EE   800000
#define DD   128
#define OUTD 64

// ---------------- device scratch (no allocations allowed) ----------------
__device__ float g_t [NN * DD];     // GEMM output (fp32) / aggregation source
__device__ float g_h1[NN * DD];
__device__ float g_h2[NN * DD];
__device__ float g_out_norm[NN];
__device__ float g_in_norm [NN];
__device__ int   g_deg_in [NN];
__device__ int   g_deg_out[NN];
__device__ int   g_row_start[NN];
__device__ int   g_cnt[NN];
__device__ int   g_col[EE];
__device__ int   g_bsum[64];
__device__ float g_Wcat[DD * DD];   // [W3 | skip_W] concatenated, 128x128

// ---------------- setup kernels ----------------
__global__ void k_zero() {
    int i = blockIdx.x * blockDim.x + threadIdx.x;
    if (i < NN) { g_deg_in[i] = 0; g_deg_out[i] = 0; g_cnt[i] = 0; }
}

__global__ void k_deg(const int* __restrict__ src, const int* __restrict__ dst) {
    int e = blockIdx.x * blockDim.x + threadIdx.x;
    if (e < EE) {
        atomicAdd(&g_deg_out[src[e]], 1);
        atomicAdd(&g_deg_in [dst[e]], 1);
    }
}

__global__ void k_norms() {
    int i = blockIdx.x * blockDim.x + threadIdx.x;
    if (i < NN) {
        int od = g_deg_out[i], id = g_deg_in[i];
        g_out_norm[i] = rsqrtf((float)(od > 1 ? od : 1));
        g_in_norm [i] = rsqrtf((float)(id > 1 ? id : 1));
    }
}

// block-wise exclusive scan of g_deg_in -> g_row_start (partial), block sums to g_bsum
__global__ void k_scan1() {
    __shared__ int sh[1024];
    int i = blockIdx.x * 1024 + threadIdx.x;
    int v = (i < NN) ? g_deg_in[i] : 0;
    sh[threadIdx.x] = v;
    __syncthreads();
    #pragma unroll
    for (int off = 1; off < 1024; off <<= 1) {
        int t = (threadIdx.x >= off) ? sh[threadIdx.x - off] : 0;
        __syncthreads();
        sh[threadIdx.x] += t;
        __syncthreads();
    }
    if (i < NN) g_row_start[i] = sh[threadIdx.x] - v;   // exclusive within block
    if (threadIdx.x == 1023) g_bsum[blockIdx.x] = sh[1023];
}

__global__ void k_scan2(int nblocks) {
    __shared__ int sh[64];
    int t = threadIdx.x;
    int v = (t < nblocks) ? g_bsum[t] : 0;
    sh[t] = v;
    __syncthreads();
    #pragma unroll
    for (int off = 1; off < 64; off <<= 1) {
        int u = (t >= off) ? sh[t - off] : 0;
        __syncthreads();
        sh[t] += u;
        __syncthreads();
    }
    if (t < nblocks) g_bsum[t] = sh[t] - v;  // exclusive
}

__global__ void k_scan3() {
    int i = blockIdx.x * blockDim.x + threadIdx.x;
    if (i < NN) g_row_start[i] += g_bsum[i >> 10];
}

__global__ void k_fill(const int* __restrict__ src, const int* __restrict__ dst) {
    int e = blockIdx.x * blockDim.x + threadIdx.x;
    if (e < EE) {
        int d = dst[e];
        int p = g_row_start[d] + atomicAdd(&g_cnt[d], 1);
        g_col[p] = src[e];
    }
}

__global__ void k_wcat(const float* __restrict__ W3, const float* __restrict__ skipW) {
    int idx = blockIdx.x * blockDim.x + threadIdx.x;
    if (idx < DD * DD) {
        int k = idx >> 7, n = idx & 127;
        g_Wcat[idx] = (n < OUTD) ? W3[k * OUTD + n] : skipW[k * OUTD + (n - OUTD)];
    }
}

// ---------------- tensor-core GEMM: C[N x 128] = A @ B, fp16 mma, fp32 accum ----
// layer 0: A = node_feats (ext), B = W1 (ext), scaleCols = 128
// layer 1: A = g_h1,             B = W2 (ext), scaleCols = 128
// layer 2: A = g_h2,             B = g_Wcat,   scaleCols = 64 (skip half unscaled)
// Block computes a 128x128 tile; K processed in two 64-chunks through smem.
// 8 warps in 2(m) x 4(n): each warp 64 rows x 32 cols via m16n8k16 HMMA.
__global__ void __launch_bounds__(256) k_gemm(const float* __restrict__ extA,
                                              const float* __restrict__ extB,
                                              int layer, int scaleCols) {
    const float* A = (layer == 0) ? extA : (layer == 1) ? g_h1 : g_h2;
    const float* B = (layer == 2) ? g_Wcat : extB;

    __shared__ __half As[128][72];    // rows x 64k (+8 pad: 144B stride, ldmatrix conflict-free)
    __shared__ __half Bs[64][136];    // k x 128n (+8 pad: 272B stride)

    int tid  = threadIdx.x;
    int lane = tid & 31;
    int wid  = tid >> 5;
    int row0 = blockIdx.x * 128;
    int mbase = (wid & 1) * 64;       // warp row offset
    int nbase = (wid >> 1) * 32;      // warp col offset

    float acc[4][4][4];
    #pragma unroll
    for (int mt = 0; mt < 4; mt++)
        #pragma unroll
        for (int nt = 0; nt < 4; nt++)
            #pragma unroll
            for (int q = 0; q < 4; q++) acc[mt][nt][q] = 0.f;

    for (int kb = 0; kb < 128; kb += 64) {
        // stage A: 128 rows x 64 k (fp32 -> fp16)
        #pragma unroll
        for (int it = 0; it < 8; ++it) {
            int idx = tid + it * 256;           // 0..2047 float4 slots
            int r   = idx >> 4;                 // 16 float4 per row
            int c4  = idx & 15;
            int gr  = row0 + r;
            float4 v = (gr < NN) ? *(const float4*)&A[gr * 128 + kb + c4 * 4]
                                 : make_float4(0.f, 0.f, 0.f, 0.f);
            __half2* dh = (__half2*)&As[r][c4 * 4];
            dh[0] = __floats2half2_rn(v.x, v.y);
            dh[1] = __floats2half2_rn(v.z, v.w);
        }
        // stage B: 64 k x 128 n (fp32 -> fp16)
        #pragma unroll
        for (int it = 0; it < 8; ++it) {
            int idx = tid + it * 256;           // 64*32 float4 slots
            int k   = idx >> 5;
            int c4  = idx & 31;
            float4 v = *(const float4*)&B[(kb + k) * 128 + c4 * 4];
            __half2* dh = (__half2*)&Bs[k][c4 * 4];
            dh[0] = __floats2half2_rn(v.x, v.y);
            dh[1] = __floats2half2_rn(v.z, v.w);
        }
        __syncthreads();

        #pragma unroll
        for (int ks = 0; ks < 4; ++ks) {        // 4 x k16
            unsigned a[4][4], b[4][2];
            int arow  = mbase + (lane & 15);
            int akofs = ks * 16 + (lane >> 4) * 8;
            #pragma unroll
            for (int mt = 0; mt < 4; ++mt) {
                unsigned ad = (unsigned)__cvta_generic_to_shared(&As[arow + mt * 16][akofs]);
                asm volatile("ldmatrix.sync.aligned.m8n8.x4.shared.b16 {%0,%1,%2,%3}, [%4];"
                    : "=r"(a[mt][0]), "=r"(a[mt][1]), "=r"(a[mt][2]), "=r"(a[mt][3]) : "r"(ad));
            }
            int bk = ks * 16 + ((lane >> 3) & 1) * 8 + (lane & 7);
            #pragma unroll
            for (int np = 0; np < 2; ++np) {    // each covers 2 n-tiles (16 cols)
                int bn = nbase + np * 16 + (lane >> 4) * 8;
                unsigned ad = (unsigned)__cvta_generic_to_shared(&Bs[bk][bn]);
                unsigned r0, r1, r2, r3;
                asm volatile("ldmatrix.sync.aligned.m8n8.x4.trans.shared.b16 {%0,%1,%2,%3}, [%4];"
                    : "=r"(r0), "=r"(r1), "=r"(r2), "=r"(r3) : "r"(ad));
                b[np * 2][0] = r0; b[np * 2][1] = r1;
                b[np * 2 + 1][0] = r2; b[np * 2 + 1][1] = r3;
            }
            #pragma unroll
            for (int mt = 0; mt < 4; ++mt)
                #pragma unroll
                for (int nt = 0; nt < 4; ++nt)
                    asm volatile("mma.sync.aligned.m16n8k16.row.col.f32.f16.f16.f32 "
                        "{%0,%1,%2,%3}, {%4,%5,%6,%7}, {%8,%9}, {%0,%1,%2,%3};"
                        : "+f"(acc[mt][nt][0]), "+f"(acc[mt][nt][1]),
                          "+f"(acc[mt][nt][2]), "+f"(acc[mt][nt][3])
                        : "r"(a[mt][0]), "r"(a[mt][1]), "r"(a[mt][2]), "r"(a[mt][3]),
                          "r"(b[nt][0]), "r"(b[nt][1]));
        }
        __syncthreads();
    }

    // epilogue: out_norm scaling on cols < scaleCols, fp32 float2 stores
    #pragma unroll
    for (int mt = 0; mt < 4; ++mt) {
        int r0g = row0 + mbase + mt * 16 + (lane >> 2);
        int r1g = r0g + 8;
        float s0 = (r0g < NN) ? g_out_norm[r0g] : 0.f;
        float s1 = (r1g < NN) ? g_out_norm[r1g] : 0.f;
        #pragma unroll
        for (int nt = 0; nt < 4; ++nt) {
            int c = nbase + nt * 8 + (lane & 3) * 2;
            float m0 = (c < scaleCols) ? s0 : 1.f;
            float m1 = (c < scaleCols) ? s1 : 1.f;
            if (r0g < NN)
                *(float2*)&g_t[r0g * 128 + c] = make_float2(acc[mt][nt][0] * m0, acc[mt][nt][1] * m0);
            if (r1g < NN)
                *(float2*)&g_t[r1g * 128 + c] = make_float2(acc[mt][nt][2] * m1, acc[mt][nt][3] * m1);
        }
    }
}

// ---------------- aggregation (CSR gather-sum, fp32) + layer epilogues ----------------
// EPI 1: h1 = relu(in_norm*acc + b1)                       (D=128, writes g_h1)
// EPI 2: h2 = relu(0.6*h1 + 0.4*(in_norm*acc + b2))        (D=128, writes g_h2)
// EPI 3: out = 0.6*(skip + skip_b) + 0.4*(in_norm*acc+b3)  (D=64,  writes extOut)
//        skip read from g_t cols 64..127 of the same row.
template <int EPI>
__global__ void __launch_bounds__(256) k_agg(const float* __restrict__ bmain,
                                             const float* __restrict__ baux,
                                             float* __restrict__ extOut) {
    constexpr int G = (EPI == 3) ? 16 : 32;   // lanes per node (float4 each)
    int node = blockIdx.x * (256 / G) + threadIdx.x / G;
    int g    = threadIdx.x & (G - 1);
    if (node >= NN) return;

    int e   = g_row_start[node];
    int end = e + g_deg_in[node];
    const float4* X = (const float4*)g_t;   // row stride = 32 float4

    float4 acc = make_float4(0.f, 0.f, 0.f, 0.f);
    for (; e + 4 <= end; e += 4) {
        int s0 = g_col[e], s1 = g_col[e + 1], s2 = g_col[e + 2], s3 = g_col[e + 3];
        float4 v0 = X[s0 * 32 + g];
        float4 v1 = X[s1 * 32 + g];
        float4 v2 = X[s2 * 32 + g];
        float4 v3 = X[s3 * 32 + g];
        acc.x += (v0.x + v1.x) + (v2.x + v3.x);
        acc.y += (v0.y + v1.y) + (v2.y + v3.y);
        acc.z += (v0.z + v1.z) + (v2.z + v3.z);
        acc.w += (v0.w + v1.w) + (v2.w + v3.w);
    }
    for (; e < end; ++e) {
        int s = g_col[e];
        float4 v = X[s * 32 + g];
        acc.x += v.x; acc.y += v.y; acc.z += v.z; acc.w += v.w;
    }

    float w = g_in_norm[node];
    float4 b = ((const float4*)bmain)[g];
    float4 r;
    if (EPI == 1) {
        r.x = fmaxf(acc.x * w + b.x, 0.f);
        r.y = fmaxf(acc.y * w + b.y, 0.f);
        r.z = fmaxf(acc.z * w + b.z, 0.f);
        r.w = fmaxf(acc.w * w + b.w, 0.f);
        ((float4*)g_h1)[node * 32 + g] = r;
    } else if (EPI == 2) {
        float4 hp = ((const float4*)g_h1)[node * 32 + g];
        r.x = fmaxf(0.6f * hp.x + 0.4f * (acc.x * w + b.x), 0.f);
        r.y = fmaxf(0.6f * hp.y + 0.4f * (acc.y * w + b.y), 0.f);
        r.z = fmaxf(0.6f * hp.z + 0.4f * (acc.z * w + b.z), 0.f);
        r.w = fmaxf(0.6f * hp.w + 0.4f * (acc.w * w + b.w), 0.f);
        ((float4*)g_h2)[node * 32 + g] = r;
    } else {
        float4 sb = ((const float4*)baux)[g];
        float4 s4 = X[node * 32 + 16 + g];   // skip half (unscaled)
        r.x = 0.6f * (s4.x + sb.x) + 0.4f * (acc.x * w + b.x);
        r.y = 0.6f * (s4.y + sb.y) + 0.4f * (acc.y * w + b.y);
        r.z = 0.6f * (s4.z + sb.z) + 0.4f * (acc.z * w + b.z);
        r.w = 0.6f * (s4.w + sb.w) + 0.4f * (acc.w * w + b.w);
        ((float4*)extOut)[node * 16 + g] = r;
    }
}

// ---------------- host launcher ----------------
extern "C" void kernel_launch(void* const* d_in, const int* in_sizes, int n_in,
                              void* d_out, int out_size) {
    const float* node_feats = (const float*)d_in[0];
    const int*   edge_index = (const int*)d_in[1];
    const float* W1    = (const float*)d_in[2];
    const float* b1    = (const float*)d_in[3];
    const float* W2    = (const float*)d_in[4];
    const float* b2    = (const float*)d_in[5];
    const float* W3    = (const float*)d_in[6];
    const float* b3    = (const float*)d_in[7];
    const float* skipW = (const float*)d_in[8];
    const float* skipb = (const float*)d_in[9];
    float* out = (float*)d_out;

    const int* src = edge_index;
    const int* dst = edge_index + EE;

    const int TB = 256;
    int nb_nodes = (NN + TB - 1) / TB;
    int nb_edges = (EE + TB - 1) / TB;
    int nb_scan  = (NN + 1023) / 1024;   // 49
    int nb_gemm  = (NN + 127) / 128;     // 391

    // order chosen so launch #4 (the one ncu captures) is the layer-0 GEMM
    k_zero <<<nb_nodes, TB>>>();
    k_deg  <<<nb_edges, TB>>>(src, dst);
    k_norms<<<nb_nodes, TB>>>();
    k_gemm <<<nb_gemm, 256>>>(node_feats, W1, 0, 128);   // layer-1 GEMM (profiled)
    k_scan1<<<nb_scan, 1024>>>();
    k_scan2<<<1, 64>>>(nb_scan);
    k_scan3<<<nb_nodes, TB>>>();
    k_fill <<<nb_edges, TB>>>(src, dst);
    k_wcat <<<(DD * DD + TB - 1) / TB, TB>>>(W3, skipW);

    k_agg<1><<<(NN + 7) / 8, 256>>>(b1, nullptr, nullptr);
    k_gemm  <<<nb_gemm, 256>>>(nullptr, W2, 1, 128);
    k_agg<2><<<(NN + 7) / 8, 256>>>(b2, nullptr, nullptr);
    k_gemm  <<<nb_gemm, 256>>>(nullptr, nullptr, 2, 64);
    k_agg<3><<<(NN + 15) / 16, 256>>>(b3, skipb, out);
}